// round 1
// baseline (speedup 1.0000x reference)
#include <cuda_runtime.h>
#include <math.h>

#define B_  4
#define L_  256
#define D_  256
#define P_  32
#define H_  8
#define HD_ 32
#define DH_ 128   // D/2

// ---- scratch (static device arrays; no allocation) ----
__device__ float g_k[B_*L_*D_];
__device__ float g_v[B_*L_*D_];
__device__ float g_q[B_*P_*L_*D_];
__device__ float g_ctx[B_*P_*L_*D_];
__device__ float g_W2q[DH_*D_];
__device__ float g_bq2[D_];

// ---------------------------------------------------------------------------
// Kernel 1: fuse W2q = w2 @ wq  (128x256), bq2 = b2 @ wq + bq
// grid 128, block 256
// ---------------------------------------------------------------------------
__global__ void fuse_w_kernel(const float* __restrict__ w2, const float* __restrict__ wq,
                              const float* __restrict__ b2, const float* __restrict__ bq) {
    int j = blockIdx.x, c = threadIdx.x;
    float acc = 0.f;
    for (int k = 0; k < D_; k++) acc = fmaf(w2[j*D_+k], wq[k*D_+c], acc);
    g_W2q[j*D_+c] = acc;
    if (j == 0) {
        float a = 0.f;
        for (int k = 0; k < D_; k++) a = fmaf(b2[k], wq[k*D_+c], a);
        g_bq2[c] = a + bq[c];
    }
}

// ---------------------------------------------------------------------------
// Kernel 2: k = ehr@wk + bk, v = ehr@wv + bv   (1024 rows)
// grid 128 (8 rows/block), block 256 (one col per thread)
// ---------------------------------------------------------------------------
__global__ void kv_kernel(const float* __restrict__ ehr,
                          const float* __restrict__ wk, const float* __restrict__ bk,
                          const float* __restrict__ wv, const float* __restrict__ bv) {
    __shared__ float sx[8*D_];
    int row0 = blockIdx.x * 8;
    int tid = threadIdx.x;
    for (int i = tid; i < 8*D_; i += 256) sx[i] = ehr[row0*D_ + i];
    __syncthreads();
    int c = tid;
    float ak[8], av[8];
    float bkc = bk[c], bvc = bv[c];
#pragma unroll
    for (int r = 0; r < 8; r++) { ak[r] = bkc; av[r] = bvc; }
    for (int d = 0; d < D_; d++) {
        float wkd = wk[d*D_+c];
        float wvd = wv[d*D_+c];
#pragma unroll
        for (int r = 0; r < 8; r++) {
            float x = sx[r*D_+d];
            ak[r] = fmaf(x, wkd, ak[r]);
            av[r] = fmaf(x, wvd, av[r]);
        }
    }
#pragma unroll
    for (int r = 0; r < 8; r++) {
        g_k[(row0+r)*D_+c] = ak[r];
        g_v[(row0+r)*D_+c] = av[r];
    }
}

// ---------------------------------------------------------------------------
// Kernel 3: per (b,p,l): tf -> gelu MLP -> q = scale*(h@W2q + bq2)
// grid 1024 (32 rows/block), block 256. Per thread: 8 rows x 4 cols.
// ---------------------------------------------------------------------------
__global__ void q_kernel(const float* __restrict__ ehr_times, const float* __restrict__ itv,
                         const float* __restrict__ w1, const float* __restrict__ b1) {
    __shared__ float sh[32*DH_];
    __shared__ float3 stf[32];
    int tid = threadIdx.x;
    int g0 = blockIdx.x * 32;
    int b  = g0 / (P_*L_);
    int p  = (g0 / L_) % P_;
    int l0 = g0 % L_;
    if (tid < 32) {
        float t = ehr_times[b*L_ + l0 + tid];
        float s = itv[(b*P_+p)*2 + 0];
        float e = itv[(b*P_+p)*2 + 1];
        float ds = t - s, de = e - t;
        float x  = ds * de;
        float sg = 1.f / (1.f + expf(-x));
        stf[tid] = make_float3(ds, de, sg);
    }
    __syncthreads();
    for (int i = tid; i < 32*DH_; i += 256) {
        int r = i >> 7, j = i & 127;
        float3 tf = stf[r];
        float z = tf.x*w1[j] + tf.y*w1[DH_+j] + tf.z*w1[2*DH_+j] + b1[j];
        sh[i] = 0.5f * z * (1.f + erff(z * 0.70710678118654752f));   // exact gelu
    }
    __syncthreads();
    int c4 = (tid & 63) * 4;
    int rg = (tid >> 6) * 8;
    float4 acc[8];
    float4 bias = *(const float4*)&g_bq2[c4];
#pragma unroll
    for (int r = 0; r < 8; r++) acc[r] = bias;
    for (int j = 0; j < DH_; j++) {
        float4 w = *(const float4*)&g_W2q[j*D_ + c4];
#pragma unroll
        for (int r = 0; r < 8; r++) {
            float x = sh[(rg+r)*DH_ + j];
            acc[r].x = fmaf(x, w.x, acc[r].x);
            acc[r].y = fmaf(x, w.y, acc[r].y);
            acc[r].z = fmaf(x, w.z, acc[r].z);
            acc[r].w = fmaf(x, w.w, acc[r].w);
        }
    }
    const float scale = 0.17677669529663687f;   // 32^-0.5
#pragma unroll
    for (int r = 0; r < 8; r++) {
        float4 o = acc[r];
        o.x *= scale; o.y *= scale; o.z *= scale; o.w *= scale;
        *(float4*)&g_q[(g0+rg+r)*D_ + c4] = o;
    }
}

// ---------------------------------------------------------------------------
// Kernel 4: attention per (b,p,h). One thread = one query row, online softmax.
// grid (H, P, B), block 256, dynamic smem = k(32KB)+v(32KB)+bias(1KB)
// ---------------------------------------------------------------------------
__global__ void attn_kernel(const float* __restrict__ ehr_times, const float* __restrict__ itv) {
    extern __shared__ float smem[];
    float* sk = smem;
    float* sv = smem + L_*HD_;
    float* sb = smem + 2*L_*HD_;
    int h = blockIdx.x, p = blockIdx.y, b = blockIdx.z;
    int tid = threadIdx.x;

    // load K,V head slices as float4 (8 float4 per row of 32)
    const float4* gk4 = (const float4*)g_k;
    const float4* gv4 = (const float4*)g_v;
    float4* sk4w = (float4*)sk;
    float4* sv4w = (float4*)sv;
    for (int i = tid; i < L_*8; i += 256) {
        int j = i >> 3, f = i & 7;
        int src = (b*L_+j)*(D_/4) + h*8 + f;
        sk4w[i] = gk4[src];
        sv4w[i] = gv4[src];
    }
    {
        float s = itv[(b*P_+p)*2 + 0];
        float e = itv[(b*P_+p)*2 + 1];
        float ctr = 0.5f*(s+e);
        float t = ehr_times[b*L_ + tid];
        sb[tid] = (t >= s && t <= e) ? -fabsf(t - ctr) : -1e30f;
    }
    __syncthreads();

    int l = tid;
    float4 qr[8];
    const float4* gq4 = (const float4*)&g_q[((b*P_+p)*L_ + l)*D_ + h*HD_];
#pragma unroll
    for (int i = 0; i < 8; i++) qr[i] = gq4[i];

    float m = -1e30f, den = 0.f;
    float4 acc[8];
#pragma unroll
    for (int i = 0; i < 8; i++) acc[i] = make_float4(0.f,0.f,0.f,0.f);

    const float4* sk4 = (const float4*)sk;
    const float4* sv4 = (const float4*)sv;
    for (int j = 0; j < L_; j++) {
        float s = sb[j];
#pragma unroll
        for (int i = 0; i < 8; i++) {
            float4 kk = sk4[j*8+i];
            s = fmaf(qr[i].x, kk.x, s);
            s = fmaf(qr[i].y, kk.y, s);
            s = fmaf(qr[i].z, kk.z, s);
            s = fmaf(qr[i].w, kk.w, s);
        }
        if (s > m) {                       // rare after warm-up
            float corr = __expf(m - s);
            den *= corr;
#pragma unroll
            for (int i = 0; i < 8; i++) {
                acc[i].x *= corr; acc[i].y *= corr;
                acc[i].z *= corr; acc[i].w *= corr;
            }
            m = s;
        }
        float pv = __expf(s - m);
        den += pv;
#pragma unroll
        for (int i = 0; i < 8; i++) {
            float4 vv = sv4[j*8+i];
            acc[i].x = fmaf(pv, vv.x, acc[i].x);
            acc[i].y = fmaf(pv, vv.y, acc[i].y);
            acc[i].z = fmaf(pv, vv.z, acc[i].z);
            acc[i].w = fmaf(pv, vv.w, acc[i].w);
        }
    }
    float inv = 1.f / den;
    float4* go = (float4*)&g_ctx[((b*P_+p)*L_ + l)*D_ + h*HD_];
#pragma unroll
    for (int i = 0; i < 8; i++) {
        float4 o = acc[i];
        o.x *= inv; o.y *= inv; o.z *= inv; o.w *= inv;
        go[i] = o;
    }
}

// ---------------------------------------------------------------------------
// Kernel 5: out = ctx @ wo + bo   (32768 x 256 x 256)
// grid 1024 (32 rows/block), block 256. Per thread: 8 rows x 4 cols.
// ---------------------------------------------------------------------------
__global__ void out_kernel(const float* __restrict__ wo, const float* __restrict__ bo,
                           float* __restrict__ out) {
    __shared__ float sx[32*D_];
    int tid = threadIdx.x;
    int row0 = blockIdx.x * 32;
    for (int i = tid; i < 32*D_; i += 256) sx[i] = g_ctx[row0*D_ + i];
    __syncthreads();
    int c4 = (tid & 63) * 4;
    int rg = (tid >> 6) * 8;
    float4 acc[8];
    float4 bias = *(const float4*)&bo[c4];
#pragma unroll
    for (int r = 0; r < 8; r++) acc[r] = bias;
    for (int k = 0; k < D_; k++) {
        float4 w = *(const float4*)&wo[k*D_ + c4];
#pragma unroll
        for (int r = 0; r < 8; r++) {
            float x = sx[(rg+r)*D_ + k];
            acc[r].x = fmaf(x, w.x, acc[r].x);
            acc[r].y = fmaf(x, w.y, acc[r].y);
            acc[r].z = fmaf(x, w.z, acc[r].z);
            acc[r].w = fmaf(x, w.w, acc[r].w);
        }
    }
#pragma unroll
    for (int r = 0; r < 8; r++)
        *(float4*)&out[(row0+rg+r)*D_ + c4] = acc[r];
}

// ---------------------------------------------------------------------------
extern "C" void kernel_launch(void* const* d_in, const int* in_sizes, int n_in,
                              void* d_out, int out_size) {
    const float* ehr       = (const float*)d_in[0];
    const float* ehr_times = (const float*)d_in[1];
    const float* itv       = (const float*)d_in[2];
    const float* w1        = (const float*)d_in[3];
    const float* b1        = (const float*)d_in[4];
    const float* w2        = (const float*)d_in[5];
    const float* b2        = (const float*)d_in[6];
    const float* wq        = (const float*)d_in[7];
    const float* bq        = (const float*)d_in[8];
    const float* wk        = (const float*)d_in[9];
    const float* bk        = (const float*)d_in[10];
    const float* wv        = (const float*)d_in[11];
    const float* bv        = (const float*)d_in[12];
    const float* wo        = (const float*)d_in[13];
    const float* bo        = (const float*)d_in[14];
    float* out = (float*)d_out;

    fuse_w_kernel<<<DH_, D_>>>(w2, wq, b2, bq);
    kv_kernel<<<B_*L_/8, 256>>>(ehr, wk, bk, wv, bv);
    q_kernel<<<B_*P_*L_/32, 256>>>(ehr_times, itv, w1, b1);

    int attn_smem = (2*L_*HD_ + L_) * (int)sizeof(float);   // 66560 B
    cudaFuncSetAttribute(attn_kernel, cudaFuncAttributeMaxDynamicSharedMemorySize, attn_smem);
    attn_kernel<<<dim3(H_, P_, B_), 256, attn_smem>>>(ehr_times, itv);

    out_kernel<<<B_*P_*L_/32, 256>>>(wo, bo, out);
}